// round 2
// baseline (speedup 1.0000x reference)
#include <cuda_runtime.h>
#include <math.h>

#define BATCH 8
#define DM    256
#define TLEN  2048
#define DIN   514
#define NL    4
#define NST   32

typedef unsigned long long u64;

// ---------------- scratch (static __device__, allocation-free) ----------------
__device__ float g_zr [BATCH*DM*TLEN];
__device__ float g_zi [BATCH*DM*TLEN];
__device__ float g_ygr[BATCH*DM*TLEN];
__device__ float g_ygi[BATCH*DM*TLEN];
__device__ float g_or [BATCH*DM*TLEN];
__device__ float g_oi [BATCH*DM*TLEN];
__device__ float g_ar [NL*DM*NST];
__device__ float g_ai [NL*DM*NST];
__device__ float g_cr [NL*DM*NST];
__device__ float g_ci [NL*DM*NST];

// ---------------- f32x2 packed helpers ----------------------------------------
__device__ __forceinline__ u64 pk(float lo, float hi) {
    u64 r; asm("mov.b64 %0, {%1, %2};" : "=l"(r) : "f"(lo), "f"(hi)); return r;
}
__device__ __forceinline__ float2 upk(u64 v) {
    float2 f; asm("mov.b64 {%0, %1}, %2;" : "=f"(f.x), "=f"(f.y) : "l"(v)); return f;
}
__device__ __forceinline__ void fma2(u64& acc, u64 a, u64 b) {
    asm("fma.rn.f32x2 %0, %1, %2, %0;" : "+l"(acc) : "l"(a), "l"(b));
}
__device__ __forceinline__ int swz(int c) { return c ^ ((c >> 4) & 7); }

__device__ __forceinline__ float gelu_tanh(float x) {
    float x3 = x * x * x;
    float t  = 0.7978845608028654f * fmaf(0.044715f, x3, x);
    float th;
    asm("tanh.approx.f32 %0, %1;" : "=f"(th) : "f"(t));
    return 0.5f * x * (1.0f + th);
}

// ---------------- S4D coefficient precompute ----------------------------------
__global__ void precompute_kernel(const float* __restrict__ log_dt,
                                  const float* __restrict__ log_A_real,
                                  const float* __restrict__ A_imag,
                                  const float* __restrict__ C_r,
                                  const float* __restrict__ C_i)
{
    int idx = blockIdx.x * blockDim.x + threadIdx.x;
    if (idx >= NL*DM*NST) return;
    int h = (idx / NST) % DM;
    int l = idx / (NST*DM);
    double dt  = exp((double)log_dt[l*DM + h]);
    double Are = -exp((double)log_A_real[idx]);
    double Aim = (double)A_imag[idx];
    double dre = Are * dt, dim = Aim * dt;
    double er  = exp(dre);
    double arr = er * cos(dim);
    double aii = er * sin(dim);
    g_ar[idx] = (float)arr;
    g_ai[idx] = (float)aii;
    double e1r = arr - 1.0, e1i = aii;
    double den = Are*Are + Aim*Aim;
    double qr  = (e1r*Are + e1i*Aim) / den;
    double qi  = (e1i*Are - e1r*Aim) / den;
    double cr  = (double)C_r[idx], ci = (double)C_i[idx];
    g_cr[idx] = (float)(cr*qr - ci*qi);
    g_ci[idx] = (float)(cr*qi + ci*qr);
}

// ---------------- shared compute core (64g x 128t tile, 4x8 microtile) --------
// sXp[kk][t] = (xr,xi), sXm[kk][t] = (xi,xr) (swizzled cols); sWc[kk][g] = (wr,wi)
__device__ __forceinline__ void cgemm_core(const u64 (*sXp)[128], const u64 (*sXm)[128],
                                           const float2 (*sWc)[65],
                                           u64 acc[4][8], int tx, int ty)
{
#pragma unroll 4
    for (int kk = 0; kk < 16; kk++) {
        u64 xp[8], xm[8];
#pragma unroll
        for (int i = 0; i < 8; i++) {
            int c = swz(tx + 16*i);
            xp[i] = sXp[kk][c];
            xm[i] = sXm[kk][c];
        }
#pragma unroll
        for (int j = 0; j < 4; j++) {
            float2 w = sWc[kk][ty + 16*j];
            u64 wrr = pk(w.x,  w.x);
            u64 wmi = pk(-w.y, w.y);
#pragma unroll
            for (int i = 0; i < 8; i++) {
                fma2(acc[j][i], wrr, xp[i]);
                fma2(acc[j][i], wmi, xm[i]);
            }
        }
    }
}

// ---------------- encoder: complex GEMM (DIN=514 -> DM), x interleaved --------
__global__ __launch_bounds__(256, 2) void encoder_gemm(const float* __restrict__ x,
    const float* __restrict__ Wr, const float* __restrict__ Wi,
    const float* __restrict__ br, const float* __restrict__ bi)
{
    __shared__ u64 sXp[16][128];
    __shared__ u64 sXm[16][128];
    __shared__ float2 sWc[16][65];
    int b  = blockIdx.z;
    int t0 = blockIdx.x * 128;
    int g0 = blockIdx.y * 64;
    int tid = threadIdx.x;
    int tx = tid & 15, ty = tid >> 4;
    u64 acc[4][8];
#pragma unroll
    for (int j = 0; j < 4; j++)
#pragma unroll
        for (int i = 0; i < 8; i++) acc[j][i] = 0ull;

    int kkp = tid >> 4, tseg = (tid & 15) * 8;   // X prep mapping
    int kw  = tid & 15, gw   = tid >> 4;         // W prep mapping

    for (int k0 = 0; k0 < DIN; k0 += 16) {
        // ---- X prep: load 8 complex (4 float4) per thread ----
        int k = k0 + kkp;
        if (k < DIN) {
            const float4* x4 = reinterpret_cast<const float4*>(x) +
                               ((((long)b*DIN + k)*TLEN + t0 + tseg) >> 1);
#pragma unroll
            for (int q = 0; q < 4; q++) {
                float4 v = x4[q];
                int c0 = tseg + 2*q;
                sXp[kkp][swz(c0  )] = pk(v.x, v.y);
                sXp[kkp][swz(c0+1)] = pk(v.z, v.w);
                sXm[kkp][swz(c0  )] = pk(v.y, v.x);
                sXm[kkp][swz(c0+1)] = pk(v.w, v.z);
            }
        } else {
#pragma unroll
            for (int q = 0; q < 8; q++) {
                sXp[kkp][swz(tseg+q)] = 0ull;
                sXm[kkp][swz(tseg+q)] = 0ull;
            }
        }
        // ---- W prep ----
#pragma unroll
        for (int s = 0; s < 4; s++) {
            int g = g0 + gw + 16*s;
            int kk = k0 + kw;
            float wr_ = 0.f, wi_ = 0.f;
            if (kk < DIN) { wr_ = Wr[(long)g*DIN + kk]; wi_ = Wi[(long)g*DIN + kk]; }
            sWc[kw][gw + 16*s] = make_float2(wr_, wi_);
        }
        __syncthreads();
        cgemm_core(sXp, sXm, sWc, acc, tx, ty);
        __syncthreads();
    }
#pragma unroll
    for (int j = 0; j < 4; j++) {
        int g = g0 + ty + 16*j;
        float bR = br[g], bI = bi[g];
#pragma unroll
        for (int i = 0; i < 8; i++) {
            int t = t0 + tx + 16*i;
            long off = ((long)b*DM + g)*TLEN + t;
            float2 f = upk(acc[j][i]);
            g_zr[off] = f.x + bR;
            g_zi[off] = f.y + bI;
        }
    }
}

// ---------------- per-layer S4D scan + D-skip + gelu (warp = one (b,h)) ------
__global__ __launch_bounds__(128) void scan_kernel(int layer, const float* __restrict__ Dvec)
{
    __shared__ float2 uS[4][32];
    __shared__ float2 prodS[4][32][34];
    int wid  = threadIdx.x >> 5;
    int lane = threadIdx.x & 31;
    int ch = blockIdx.x * 4 + wid;
    int b  = ch >> 8;
    int h  = ch & 255;
    int pidx = (layer*DM + h)*NST + lane;
    float ar = g_ar[pidx], ai = g_ai[pidx];
    float cr = g_cr[pidx], ci = g_ci[pidx];
    float Dh = Dvec[layer*DM + h];
    long base = ((long)b*DM + h)*TLEN;
    const float* zr = g_zr + base;
    const float* zi = g_zi + base;
    float* yro = g_ygr + base;
    float* yio = g_ygi + base;

    float sr = 0.f, si = 0.f;
    for (int t0 = 0; t0 < TLEN; t0 += 32) {
        float ur_l = zr[t0 + lane];
        float ui_l = zi[t0 + lane];
        uS[wid][lane] = make_float2(ur_l, ui_l);
        __syncwarp();
#pragma unroll
        for (int j = 0; j < 32; j++) {
            float2 u = uS[wid][j];
            float nsr = fmaf(ar, sr, u.x); nsr = fmaf(-ai, si, nsr);
            float nsi = fmaf(ar, si, u.y); nsi = fmaf( ai, sr, nsi);
            sr = nsr; si = nsi;
            float pr = cr * sr; pr = fmaf(-ci, si, pr);
            float pi = cr * si; pi = fmaf( ci, sr, pi);
            prodS[wid][j][lane] = make_float2(pr, pi);
        }
        __syncwarp();
        float yr = 0.f, yi = 0.f;
#pragma unroll
        for (int q = 0; q < 32; q++) {
            float2 v = prodS[wid][lane][q];
            yr += v.x; yi += v.y;
        }
        yr = fmaf(Dh, ur_l, yr);
        yi = fmaf(Dh, ui_l, yi);
        yro[t0 + lane] = gelu_tanh(yr);
        yio[t0 + lane] = gelu_tanh(yi);
        __syncwarp();
    }
}

// ---------------- per-layer pointwise complex GEMM (DM -> DM) -----------------
__global__ __launch_bounds__(256, 2) void outlin_gemm(int l,
    const float* __restrict__ Wr, const float* __restrict__ Wi,
    const float* __restrict__ br, const float* __restrict__ bi)
{
    __shared__ u64 sXp[16][128];
    __shared__ u64 sXm[16][128];
    __shared__ float2 sWc[16][65];
    int b  = blockIdx.z;
    int t0 = blockIdx.x * 128;
    int g0 = blockIdx.y * 64;
    int tid = threadIdx.x;
    int tx = tid & 15, ty = tid >> 4;
    u64 acc[4][8];
#pragma unroll
    for (int j = 0; j < 4; j++)
#pragma unroll
        for (int i = 0; i < 8; i++) acc[j][i] = 0ull;

    const float* wrp = Wr + (long)l*DM*DM;
    const float* wip = Wi + (long)l*DM*DM;
    int kkp = tid >> 4, tseg = (tid & 15) * 8;
    int kw  = tid & 15, gw   = tid >> 4;

    for (int k0 = 0; k0 < DM; k0 += 16) {
        long xbase = ((long)b*DM + k0 + kkp)*TLEN + t0 + tseg;
        const float4* yr4 = reinterpret_cast<const float4*>(g_ygr + xbase);
        const float4* yi4 = reinterpret_cast<const float4*>(g_ygi + xbase);
#pragma unroll
        for (int q = 0; q < 2; q++) {
            float4 r = yr4[q], im = yi4[q];
            int c0 = tseg + 4*q;
            sXp[kkp][swz(c0  )] = pk(r.x, im.x);
            sXp[kkp][swz(c0+1)] = pk(r.y, im.y);
            sXp[kkp][swz(c0+2)] = pk(r.z, im.z);
            sXp[kkp][swz(c0+3)] = pk(r.w, im.w);
            sXm[kkp][swz(c0  )] = pk(im.x, r.x);
            sXm[kkp][swz(c0+1)] = pk(im.y, r.y);
            sXm[kkp][swz(c0+2)] = pk(im.z, r.z);
            sXm[kkp][swz(c0+3)] = pk(im.w, r.w);
        }
#pragma unroll
        for (int s = 0; s < 4; s++) {
            int g = g0 + gw + 16*s;
            int kk = k0 + kw;
            sWc[kw][gw + 16*s] = make_float2(wrp[(long)g*DM + kk], wip[(long)g*DM + kk]);
        }
        __syncthreads();
        cgemm_core(sXp, sXm, sWc, acc, tx, ty);
        __syncthreads();
    }
#pragma unroll
    for (int j = 0; j < 4; j++) {
        int g = g0 + ty + 16*j;
        float bR = br[l*DM + g], bI = bi[l*DM + g];
#pragma unroll
        for (int i = 0; i < 8; i++) {
            int t = t0 + tx + 16*i;
            long off = ((long)b*DM + g)*TLEN + t;
            float2 f = upk(acc[j][i]);
            g_or[off] = f.x + bR;
            g_oi[off] = f.y + bI;
        }
    }
}

// ---------------- residual + complex LayerNorm over channels ------------------
__global__ __launch_bounds__(256) void ln_kernel(int l,
    const float* __restrict__ gamma_r, const float* __restrict__ gamma_i,
    const float* __restrict__ beta_r,  const float* __restrict__ beta_i)
{
    int b  = blockIdx.y;
    int t0 = blockIdx.x * 32;
    int tt = threadIdx.x & 31;
    int gg = threadIdx.x >> 5;
    int t  = t0 + tt;

    float vr[32], vi[32];
    float sr = 0.f, qr = 0.f, si = 0.f, qi = 0.f;
#pragma unroll
    for (int j = 0; j < 32; j++) {
        int g = gg*32 + j;
        long off = ((long)b*DM + g)*TLEN + t;
        float r  = g_zr[off] + g_or[off];
        float i_ = g_zi[off] + g_oi[off];
        vr[j] = r; vi[j] = i_;
        sr += r;  qr = fmaf(r, r, qr);
        si += i_; qi = fmaf(i_, i_, qi);
    }
    __shared__ float red[4][8][32];
    red[0][gg][tt] = sr; red[1][gg][tt] = qr;
    red[2][gg][tt] = si; red[3][gg][tt] = qi;
    __syncthreads();
    float tsr = 0.f, tqr = 0.f, tsi = 0.f, tqi = 0.f;
#pragma unroll
    for (int k = 0; k < 8; k++) {
        tsr += red[0][k][tt]; tqr += red[1][k][tt];
        tsi += red[2][k][tt]; tqi += red[3][k][tt];
    }
    float mr  = tsr * (1.f/DM), mi_ = tsi * (1.f/DM);
    float var_r = tqr * (1.f/DM) - mr*mr;
    float var_i = tqi * (1.f/DM) - mi_*mi_;
    float rr = rsqrtf(var_r + 1e-5f);
    float ri = rsqrtf(var_i + 1e-5f);
#pragma unroll
    for (int j = 0; j < 32; j++) {
        int g = gg*32 + j;
        long off = ((long)b*DM + g)*TLEN + t;
        g_zr[off] = (vr[j] - mr)  * rr * gamma_r[l*DM + g] + beta_r[l*DM + g];
        g_zi[off] = (vi[j] - mi_) * ri * gamma_i[l*DM + g] + beta_i[l*DM + g];
    }
}

// ---------------- decoder: complex GEMM (DM -> DIN), interleaved output -------
__global__ __launch_bounds__(256, 2) void decoder_gemm(
    const float* __restrict__ Wr, const float* __restrict__ Wi,
    const float* __restrict__ br, const float* __restrict__ bi,
    float2* __restrict__ out)
{
    __shared__ u64 sXp[16][128];
    __shared__ u64 sXm[16][128];
    __shared__ float2 sWc[16][65];
    int b  = blockIdx.z;
    int t0 = blockIdx.x * 128;
    int g0 = blockIdx.y * 64;
    int tid = threadIdx.x;
    int tx = tid & 15, ty = tid >> 4;
    u64 acc[4][8];
#pragma unroll
    for (int j = 0; j < 4; j++)
#pragma unroll
        for (int i = 0; i < 8; i++) acc[j][i] = 0ull;

    int kkp = tid >> 4, tseg = (tid & 15) * 8;
    int kw  = tid & 15, gw   = tid >> 4;

    for (int k0 = 0; k0 < DM; k0 += 16) {
        long xbase = ((long)b*DM + k0 + kkp)*TLEN + t0 + tseg;
        const float4* zr4 = reinterpret_cast<const float4*>(g_zr + xbase);
        const float4* zi4 = reinterpret_cast<const float4*>(g_zi + xbase);
#pragma unroll
        for (int q = 0; q < 2; q++) {
            float4 r = zr4[q], im = zi4[q];
            int c0 = tseg + 4*q;
            sXp[kkp][swz(c0  )] = pk(r.x, im.x);
            sXp[kkp][swz(c0+1)] = pk(r.y, im.y);
            sXp[kkp][swz(c0+2)] = pk(r.z, im.z);
            sXp[kkp][swz(c0+3)] = pk(r.w, im.w);
            sXm[kkp][swz(c0  )] = pk(im.x, r.x);
            sXm[kkp][swz(c0+1)] = pk(im.y, r.y);
            sXm[kkp][swz(c0+2)] = pk(im.z, r.z);
            sXm[kkp][swz(c0+3)] = pk(im.w, r.w);
        }
#pragma unroll
        for (int s = 0; s < 4; s++) {
            int g = g0 + gw + 16*s;
            int kk = k0 + kw;
            float wr_ = 0.f, wi_ = 0.f;
            if (g < DIN) { wr_ = Wr[(long)g*DM + kk]; wi_ = Wi[(long)g*DM + kk]; }
            sWc[kw][gw + 16*s] = make_float2(wr_, wi_);
        }
        __syncthreads();
        cgemm_core(sXp, sXm, sWc, acc, tx, ty);
        __syncthreads();
    }
#pragma unroll
    for (int j = 0; j < 4; j++) {
        int g = g0 + ty + 16*j;
        if (g >= DIN) continue;
        float bR = br[g], bI = bi[g];
#pragma unroll
        for (int i = 0; i < 8; i++) {
            int t = t0 + tx + 16*i;
            float2 f = upk(acc[j][i]);
            out[((long)b*DIN + g)*TLEN + t] = make_float2(f.x + bR, f.y + bI);
        }
    }
}

// ---------------- launch ------------------------------------------------------
extern "C" void kernel_launch(void* const* d_in, const int* in_sizes, int n_in,
                              void* d_out, int out_size)
{
    const float* x          = (const float*)d_in[0];
    const float* enc_Wr     = (const float*)d_in[1];
    const float* enc_Wi     = (const float*)d_in[2];
    const float* enc_br     = (const float*)d_in[3];
    const float* enc_bi     = (const float*)d_in[4];
    const float* log_dt     = (const float*)d_in[5];
    const float* log_A_real = (const float*)d_in[6];
    const float* A_imag     = (const float*)d_in[7];
    const float* C_r        = (const float*)d_in[8];
    const float* C_i        = (const float*)d_in[9];
    const float* Dvec       = (const float*)d_in[10];
    const float* out_Wr     = (const float*)d_in[11];
    const float* out_Wi     = (const float*)d_in[12];
    const float* out_br     = (const float*)d_in[13];
    const float* out_bi     = (const float*)d_in[14];
    const float* ln_gamma_r = (const float*)d_in[15];
    const float* ln_gamma_i = (const float*)d_in[16];
    const float* ln_beta_r  = (const float*)d_in[17];
    const float* ln_beta_i  = (const float*)d_in[18];
    const float* dec_Wr     = (const float*)d_in[19];
    const float* dec_Wi     = (const float*)d_in[20];
    const float* dec_br     = (const float*)d_in[21];
    const float* dec_bi     = (const float*)d_in[22];

    precompute_kernel<<<(NL*DM*NST + 255)/256, 256>>>(log_dt, log_A_real, A_imag, C_r, C_i);

    encoder_gemm<<<dim3(TLEN/128, DM/64, BATCH), 256>>>(x, enc_Wr, enc_Wi, enc_br, enc_bi);

    for (int l = 0; l < NL; l++) {
        scan_kernel<<<(BATCH*DM)/4, 128>>>(l, Dvec);
        outlin_gemm<<<dim3(TLEN/128, DM/64, BATCH), 256>>>(l, out_Wr, out_Wi, out_br, out_bi);
        ln_kernel<<<dim3(TLEN/32, BATCH), 256>>>(l, ln_gamma_r, ln_gamma_i, ln_beta_r, ln_beta_i);
    }

    decoder_gemm<<<dim3(TLEN/128, (DIN + 63)/64, BATCH), 256>>>(dec_Wr, dec_Wi, dec_br, dec_bi,
                                                                (float2*)d_out);
}

// round 3
// speedup vs baseline: 1.1751x; 1.1751x over previous
#include <cuda_runtime.h>
#include <math.h>

#define BATCH 8
#define DM    256
#define TLEN  2048
#define DIN   514
#define NL    4
#define NST   32

typedef unsigned long long u64;

// ---------------- scratch (static __device__, allocation-free) ----------------
__device__ float g_zr [BATCH*DM*TLEN];
__device__ float g_zi [BATCH*DM*TLEN];
__device__ float g_ygr[BATCH*DM*TLEN];
__device__ float g_ygi[BATCH*DM*TLEN];
__device__ float g_or [BATCH*DM*TLEN];
__device__ float g_oi [BATCH*DM*TLEN];
__device__ float g_ar [NL*DM*NST];
__device__ float g_ai [NL*DM*NST];
__device__ float g_cr [NL*DM*NST];
__device__ float g_ci [NL*DM*NST];

// ---------------- f32x2 packed helpers ----------------------------------------
__device__ __forceinline__ u64 pk(float lo, float hi) {
    u64 r; asm("mov.b64 %0, {%1, %2};" : "=l"(r) : "f"(lo), "f"(hi)); return r;
}
__device__ __forceinline__ float2 upk(u64 v) {
    float2 f; asm("mov.b64 {%0, %1}, %2;" : "=f"(f.x), "=f"(f.y) : "l"(v)); return f;
}
__device__ __forceinline__ void fma2(u64& acc, u64 a, u64 b) {
    asm("fma.rn.f32x2 %0, %1, %2, %0;" : "+l"(acc) : "l"(a), "l"(b));
}

__device__ __forceinline__ float gelu_tanh(float x) {
    float x3 = x * x * x;
    float t  = 0.7978845608028654f * fmaf(0.044715f, x3, x);
    float th;
    asm("tanh.approx.f32 %0, %1;" : "=f"(th) : "f"(t));
    return 0.5f * x * (1.0f + th);
}

// ---------------- S4D coefficient precompute ----------------------------------
__global__ void precompute_kernel(const float* __restrict__ log_dt,
                                  const float* __restrict__ log_A_real,
                                  const float* __restrict__ A_imag,
                                  const float* __restrict__ C_r,
                                  const float* __restrict__ C_i)
{
    int idx = blockIdx.x * blockDim.x + threadIdx.x;
    if (idx >= NL*DM*NST) return;
    int h = (idx / NST) % DM;
    int l = idx / (NST*DM);
    double dt  = exp((double)log_dt[l*DM + h]);
    double Are = -exp((double)log_A_real[idx]);
    double Aim = (double)A_imag[idx];
    double dre = Are * dt, dim = Aim * dt;
    double er  = exp(dre);
    double arr = er * cos(dim);
    double aii = er * sin(dim);
    g_ar[idx] = (float)arr;
    g_ai[idx] = (float)aii;
    double e1r = arr - 1.0, e1i = aii;
    double den = Are*Are + Aim*Aim;
    double qr  = (e1r*Are + e1i*Aim) / den;
    double qi  = (e1i*Are - e1r*Aim) / den;
    double cr  = (double)C_r[idx], ci = (double)C_i[idx];
    g_cr[idx] = (float)(cr*qr - ci*qi);
    g_ci[idx] = (float)(cr*qi + ci*qr);
}

// ---------------- shared compute core ------------------------------------------
// Tile: 64 g x 128 t (64 t-pairs). Thread microtile: 4 g x 4 t-pairs.
// sXr[kk][p] = (xr(2p), xr(2p+1)), sXi likewise.
// sWrr[kk][g] = (wr,wr), sWpi = (wi,wi), sWni = (-wi,-wi).
// accR[j][i] accumulates (R(t),R(t+1)); accI likewise for imag.
__device__ __forceinline__ void cgemm_core(const u64 (*sXr)[64], const u64 (*sXi)[64],
                                           const u64 (*sWrr)[65], const u64 (*sWpi)[65],
                                           const u64 (*sWni)[65],
                                           u64 accR[4][4], u64 accI[4][4], int tx, int ty)
{
#pragma unroll 4
    for (int kk = 0; kk < 16; kk++) {
        u64 xr[4], xi[4];
#pragma unroll
        for (int i = 0; i < 4; i++) {
            int c = tx + 16*i;
            xr[i] = sXr[kk][c];
            xi[i] = sXi[kk][c];
        }
#pragma unroll
        for (int j = 0; j < 4; j++) {
            int gcol = ty + 16*j;
            u64 wrr = sWrr[kk][gcol];
            u64 wpi = sWpi[kk][gcol];
            u64 wni = sWni[kk][gcol];
#pragma unroll
            for (int i = 0; i < 4; i++) {
                fma2(accR[j][i], wrr, xr[i]);
                fma2(accR[j][i], wni, xi[i]);
                fma2(accI[j][i], wrr, xi[i]);
                fma2(accI[j][i], wpi, xr[i]);
            }
        }
    }
}

// ---------------- encoder: complex GEMM (DIN=514 -> DM), x interleaved --------
__global__ __launch_bounds__(256, 2) void encoder_gemm(const float* __restrict__ x,
    const float* __restrict__ Wr, const float* __restrict__ Wi,
    const float* __restrict__ br, const float* __restrict__ bi)
{
    __shared__ u64 sXr[16][64];
    __shared__ u64 sXi[16][64];
    __shared__ u64 sWrr[16][65];
    __shared__ u64 sWpi[16][65];
    __shared__ u64 sWni[16][65];
    int b  = blockIdx.z;
    int t0 = blockIdx.x * 128;
    int g0 = blockIdx.y * 64;
    int tid = threadIdx.x;
    int tx = tid & 15, ty = tid >> 4;
    u64 accR[4][4], accI[4][4];
#pragma unroll
    for (int j = 0; j < 4; j++)
#pragma unroll
        for (int i = 0; i < 4; i++) { accR[j][i] = 0ull; accI[j][i] = 0ull; }

    int kkp = tid >> 4, tq = tid & 15;   // X prep: row kkp, pair cols tq+16q
    int kw  = tid & 15, gw  = tid >> 4;  // W prep

    for (int k0 = 0; k0 < DIN; k0 += 16) {
        int k = k0 + kkp;
        if (k < DIN) {
            const float4* x4 = reinterpret_cast<const float4*>(
                x + 2*(((long)b*DIN + k)*TLEN + t0));
#pragma unroll
            for (int q = 0; q < 4; q++) {
                int c = tq + 16*q;
                float4 v = x4[c];               // (r0,i0,r1,i1) at t=2c
                sXr[kkp][c] = pk(v.x, v.z);
                sXi[kkp][c] = pk(v.y, v.w);
            }
        } else {
#pragma unroll
            for (int q = 0; q < 4; q++) {
                int c = tq + 16*q;
                sXr[kkp][c] = 0ull;
                sXi[kkp][c] = 0ull;
            }
        }
#pragma unroll
        for (int s = 0; s < 4; s++) {
            int gg = gw + 16*s;
            int kk = k0 + kw;
            float wr_ = 0.f, wi_ = 0.f;
            if (kk < DIN) { wr_ = Wr[(long)(g0+gg)*DIN + kk]; wi_ = Wi[(long)(g0+gg)*DIN + kk]; }
            sWrr[kw][gg] = pk(wr_, wr_);
            sWpi[kw][gg] = pk(wi_, wi_);
            sWni[kw][gg] = pk(-wi_, -wi_);
        }
        __syncthreads();
        cgemm_core(sXr, sXi, sWrr, sWpi, sWni, accR, accI, tx, ty);
        __syncthreads();
    }
#pragma unroll
    for (int j = 0; j < 4; j++) {
        int g = g0 + ty + 16*j;
        float bR = br[g], bI = bi[g];
#pragma unroll
        for (int i = 0; i < 4; i++) {
            int t = t0 + 2*(tx + 16*i);
            long off = ((long)b*DM + g)*TLEN + t;
            float2 fR = upk(accR[j][i]);
            float2 fI = upk(accI[j][i]);
            *reinterpret_cast<float2*>(g_zr + off) = make_float2(fR.x + bR, fR.y + bR);
            *reinterpret_cast<float2*>(g_zi + off) = make_float2(fI.x + bI, fI.y + bI);
        }
    }
}

// ---------------- per-layer S4D scan + D-skip + gelu (warp = one (b,h)) ------
__global__ __launch_bounds__(128) void scan_kernel(int layer, const float* __restrict__ Dvec)
{
    __shared__ float2 uS[4][32];
    __shared__ float2 prodS[4][32][34];
    int wid  = threadIdx.x >> 5;
    int lane = threadIdx.x & 31;
    int ch = blockIdx.x * 4 + wid;
    int b  = ch >> 8;
    int h  = ch & 255;
    int pidx = (layer*DM + h)*NST + lane;
    float ar = g_ar[pidx], ai = g_ai[pidx];
    float cr = g_cr[pidx], ci = g_ci[pidx];
    float Dh = Dvec[layer*DM + h];
    long base = ((long)b*DM + h)*TLEN;
    const float* zr = g_zr + base;
    const float* zi = g_zi + base;
    float* yro = g_ygr + base;
    float* yio = g_ygi + base;

    float sr = 0.f, si = 0.f;
    for (int t0 = 0; t0 < TLEN; t0 += 32) {
        float ur_l = zr[t0 + lane];
        float ui_l = zi[t0 + lane];
        uS[wid][lane] = make_float2(ur_l, ui_l);
        __syncwarp();
#pragma unroll
        for (int j = 0; j < 32; j++) {
            float2 u = uS[wid][j];
            float nsr = fmaf(ar, sr, u.x); nsr = fmaf(-ai, si, nsr);
            float nsi = fmaf(ar, si, u.y); nsi = fmaf( ai, sr, nsi);
            sr = nsr; si = nsi;
            float pr = cr * sr; pr = fmaf(-ci, si, pr);
            float pi = cr * si; pi = fmaf( ci, sr, pi);
            prodS[wid][j][lane] = make_float2(pr, pi);
        }
        __syncwarp();
        float yr = 0.f, yi = 0.f;
#pragma unroll
        for (int q = 0; q < 32; q++) {
            float2 v = prodS[wid][lane][q];
            yr += v.x; yi += v.y;
        }
        yr = fmaf(Dh, ur_l, yr);
        yi = fmaf(Dh, ui_l, yi);
        yro[t0 + lane] = gelu_tanh(yr);
        yio[t0 + lane] = gelu_tanh(yi);
        __syncwarp();
    }
}

// ---------------- per-layer pointwise complex GEMM (DM -> DM) -----------------
__global__ __launch_bounds__(256, 2) void outlin_gemm(int l,
    const float* __restrict__ Wr, const float* __restrict__ Wi,
    const float* __restrict__ br, const float* __restrict__ bi)
{
    __shared__ u64 sXr[16][64];
    __shared__ u64 sXi[16][64];
    __shared__ u64 sWrr[16][65];
    __shared__ u64 sWpi[16][65];
    __shared__ u64 sWni[16][65];
    int b  = blockIdx.z;
    int t0 = blockIdx.x * 128;
    int g0 = blockIdx.y * 64;
    int tid = threadIdx.x;
    int tx = tid & 15, ty = tid >> 4;
    u64 accR[4][4], accI[4][4];
#pragma unroll
    for (int j = 0; j < 4; j++)
#pragma unroll
        for (int i = 0; i < 4; i++) { accR[j][i] = 0ull; accI[j][i] = 0ull; }

    const float* wrp = Wr + (long)l*DM*DM;
    const float* wip = Wi + (long)l*DM*DM;
    int kkp = tid >> 4, tq = tid & 15;
    int kw  = tid & 15, gw  = tid >> 4;

    for (int k0 = 0; k0 < DM; k0 += 16) {
        long xbase = ((long)b*DM + k0 + kkp)*TLEN + t0;
        const u64* yr2 = reinterpret_cast<const u64*>(g_ygr + xbase);
        const u64* yi2 = reinterpret_cast<const u64*>(g_ygi + xbase);
#pragma unroll
        for (int q = 0; q < 4; q++) {
            int c = tq + 16*q;
            sXr[kkp][c] = yr2[c];
            sXi[kkp][c] = yi2[c];
        }
#pragma unroll
        for (int s = 0; s < 4; s++) {
            int gg = gw + 16*s;
            int kk = k0 + kw;
            float wr_ = wrp[(long)(g0+gg)*DM + kk];
            float wi_ = wip[(long)(g0+gg)*DM + kk];
            sWrr[kw][gg] = pk(wr_, wr_);
            sWpi[kw][gg] = pk(wi_, wi_);
            sWni[kw][gg] = pk(-wi_, -wi_);
        }
        __syncthreads();
        cgemm_core(sXr, sXi, sWrr, sWpi, sWni, accR, accI, tx, ty);
        __syncthreads();
    }
#pragma unroll
    for (int j = 0; j < 4; j++) {
        int g = g0 + ty + 16*j;
        float bR = br[l*DM + g], bI = bi[l*DM + g];
#pragma unroll
        for (int i = 0; i < 4; i++) {
            int t = t0 + 2*(tx + 16*i);
            long off = ((long)b*DM + g)*TLEN + t;
            float2 fR = upk(accR[j][i]);
            float2 fI = upk(accI[j][i]);
            *reinterpret_cast<float2*>(g_or + off) = make_float2(fR.x + bR, fR.y + bR);
            *reinterpret_cast<float2*>(g_oi + off) = make_float2(fI.x + bI, fI.y + bI);
        }
    }
}

// ---------------- residual + complex LayerNorm over channels ------------------
__global__ __launch_bounds__(256) void ln_kernel(int l,
    const float* __restrict__ gamma_r, const float* __restrict__ gamma_i,
    const float* __restrict__ beta_r,  const float* __restrict__ beta_i)
{
    int b  = blockIdx.y;
    int t0 = blockIdx.x * 32;
    int tt = threadIdx.x & 31;
    int gg = threadIdx.x >> 5;
    int t  = t0 + tt;

    float vr[32], vi[32];
    float sr = 0.f, qr = 0.f, si = 0.f, qi = 0.f;
#pragma unroll
    for (int j = 0; j < 32; j++) {
        int g = gg*32 + j;
        long off = ((long)b*DM + g)*TLEN + t;
        float r  = g_zr[off] + g_or[off];
        float i_ = g_zi[off] + g_oi[off];
        vr[j] = r; vi[j] = i_;
        sr += r;  qr = fmaf(r, r, qr);
        si += i_; qi = fmaf(i_, i_, qi);
    }
    __shared__ float red[4][8][32];
    red[0][gg][tt] = sr; red[1][gg][tt] = qr;
    red[2][gg][tt] = si; red[3][gg][tt] = qi;
    __syncthreads();
    float tsr = 0.f, tqr = 0.f, tsi = 0.f, tqi = 0.f;
#pragma unroll
    for (int k = 0; k < 8; k++) {
        tsr += red[0][k][tt]; tqr += red[1][k][tt];
        tsi += red[2][k][tt]; tqi += red[3][k][tt];
    }
    float mr  = tsr * (1.f/DM), mi_ = tsi * (1.f/DM);
    float var_r = tqr * (1.f/DM) - mr*mr;
    float var_i = tqi * (1.f/DM) - mi_*mi_;
    float rr = rsqrtf(var_r + 1e-5f);
    float ri = rsqrtf(var_i + 1e-5f);
#pragma unroll
    for (int j = 0; j < 32; j++) {
        int g = gg*32 + j;
        long off = ((long)b*DM + g)*TLEN + t;
        g_zr[off] = (vr[j] - mr)  * rr * gamma_r[l*DM + g] + beta_r[l*DM + g];
        g_zi[off] = (vi[j] - mi_) * ri * gamma_i[l*DM + g] + beta_i[l*DM + g];
    }
}

// ---------------- decoder: complex GEMM (DM -> DIN), interleaved output -------
__global__ __launch_bounds__(256, 2) void decoder_gemm(
    const float* __restrict__ Wr, const float* __restrict__ Wi,
    const float* __restrict__ br, const float* __restrict__ bi,
    float4* __restrict__ out)
{
    __shared__ u64 sXr[16][64];
    __shared__ u64 sXi[16][64];
    __shared__ u64 sWrr[16][65];
    __shared__ u64 sWpi[16][65];
    __shared__ u64 sWni[16][65];
    int b  = blockIdx.z;
    int t0 = blockIdx.x * 128;
    int g0 = blockIdx.y * 64;
    int tid = threadIdx.x;
    int tx = tid & 15, ty = tid >> 4;
    u64 accR[4][4], accI[4][4];
#pragma unroll
    for (int j = 0; j < 4; j++)
#pragma unroll
        for (int i = 0; i < 4; i++) { accR[j][i] = 0ull; accI[j][i] = 0ull; }

    int kkp = tid >> 4, tq = tid & 15;
    int kw  = tid & 15, gw  = tid >> 4;

    for (int k0 = 0; k0 < DM; k0 += 16) {
        long xbase = ((long)b*DM + k0 + kkp)*TLEN + t0;
        const u64* zr2 = reinterpret_cast<const u64*>(g_zr + xbase);
        const u64* zi2 = reinterpret_cast<const u64*>(g_zi + xbase);
#pragma unroll
        for (int q = 0; q < 4; q++) {
            int c = tq + 16*q;
            sXr[kkp][c] = zr2[c];
            sXi[kkp][c] = zi2[c];
        }
#pragma unroll
        for (int s = 0; s < 4; s++) {
            int gg = gw + 16*s;
            int g  = g0 + gg;
            int kk = k0 + kw;
            float wr_ = 0.f, wi_ = 0.f;
            if (g < DIN) { wr_ = Wr[(long)g*DM + kk]; wi_ = Wi[(long)g*DM + kk]; }
            sWrr[kw][gg] = pk(wr_, wr_);
            sWpi[kw][gg] = pk(wi_, wi_);
            sWni[kw][gg] = pk(-wi_, -wi_);
        }
        __syncthreads();
        cgemm_core(sXr, sXi, sWrr, sWpi, sWni, accR, accI, tx, ty);
        __syncthreads();
    }
#pragma unroll
    for (int j = 0; j < 4; j++) {
        int g = g0 + ty + 16*j;
        if (g >= DIN) continue;
        float bR = br[g], bI = bi[g];
#pragma unroll
        for (int i = 0; i < 4; i++) {
            int t = t0 + 2*(tx + 16*i);
            float2 fR = upk(accR[j][i]);
            float2 fI = upk(accI[j][i]);
            // interleaved (re,im) per t: two t's -> one float4
            out[(((long)b*DIN + g)*TLEN + t) >> 1] =
                make_float4(fR.x + bR, fI.x + bI, fR.y + bR, fI.y + bI);
        }
    }
}

// ---------------- launch ------------------------------------------------------
extern "C" void kernel_launch(void* const* d_in, const int* in_sizes, int n_in,
                              void* d_out, int out_size)
{
    const float* x          = (const float*)d_in[0];
    const float* enc_Wr     = (const float*)d_in[1];
    const float* enc_Wi     = (const float*)d_in[2];
    const float* enc_br     = (const float*)d_in[3];
    const float* enc_bi     = (const float*)d_in[4];
    const float* log_dt     = (const float*)d_in[5];
    const float* log_A_real = (const float*)d_in[6];
    const float* A_imag     = (const float*)d_in[7];
    const float* C_r        = (const float*)d_in[8];
    const float* C_i        = (const float*)d_in[9];
    const float* Dvec       = (const float*)d_in[10];
    const float* out_Wr     = (const float*)d_in[11];
    const float* out_Wi     = (const float*)d_in[12];
    const float* out_br     = (const float*)d_in[13];
    const float* out_bi     = (const float*)d_in[14];
    const float* ln_gamma_r = (const float*)d_in[15];
    const float* ln_gamma_i = (const float*)d_in[16];
    const float* ln_beta_r  = (const float*)d_in[17];
    const float* ln_beta_i  = (const float*)d_in[18];
    const float* dec_Wr     = (const float*)d_in[19];
    const float* dec_Wi     = (const float*)d_in[20];
    const float* dec_br     = (const float*)d_in[21];
    const float* dec_bi     = (const float*)d_in[22];

    precompute_kernel<<<(NL*DM*NST + 255)/256, 256>>>(log_dt, log_A_real, A_imag, C_r, C_i);

    encoder_gemm<<<dim3(TLEN/128, DM/64, BATCH), 256>>>(x, enc_Wr, enc_Wi, enc_br, enc_bi);

    for (int l = 0; l < NL; l++) {
        scan_kernel<<<(BATCH*DM)/4, 128>>>(l, Dvec);
        outlin_gemm<<<dim3(TLEN/128, DM/64, BATCH), 256>>>(l, out_Wr, out_Wi, out_br, out_bi);
        ln_kernel<<<dim3(TLEN/32, BATCH), 256>>>(l, ln_gamma_r, ln_gamma_i, ln_beta_r, ln_beta_i);
    }

    decoder_gemm<<<dim3(TLEN/128, (DIN + 63)/64, BATCH), 256>>>(dec_Wr, dec_Wi, dec_br, dec_bi,
                                                                (float4*)d_out);
}

// round 4
// speedup vs baseline: 1.2307x; 1.0473x over previous
#include <cuda_runtime.h>
#include <math.h>

#define BATCH 8
#define DM    256
#define TLEN  2048
#define TP    (TLEN/2)
#define DIN   514
#define KENC  520          // DIN padded to multiple of 8
#define GDEC  576          // DIN padded to multiple of 64
#define NL    4
#define NST   32

typedef unsigned long long u64;

// ---------------- scratch (static __device__, allocation-free) ----------------
__device__ __align__(16) float g_zr [BATCH*DM*TLEN];
__device__ __align__(16) float g_zi [BATCH*DM*TLEN];
__device__ __align__(16) float g_ygr[BATCH*DM*TLEN];
__device__ __align__(16) float g_ygi[BATCH*DM*TLEN];
__device__ __align__(16) float g_or [BATCH*DM*TLEN];
__device__ __align__(16) float g_oi [BATCH*DM*TLEN];
__device__ float g_ar [NL*DM*NST];
__device__ float g_ai [NL*DM*NST];
__device__ float g_cr [NL*DM*NST];
__device__ float g_ci [NL*DM*NST];
// split/padded encoder input, u64 = (f(t), f(t+1))
__device__ __align__(16) u64 g_xr[(long)BATCH*KENC*TP];
__device__ __align__(16) u64 g_xi[(long)BATCH*KENC*TP];
// prepacked weights, [k][g] layout, u64 broadcasts
__device__ __align__(16) u64 g_weRR[KENC*DM], g_wePI[KENC*DM], g_weNI[KENC*DM];
__device__ __align__(16) u64 g_woRR[NL*DM*DM], g_woPI[NL*DM*DM], g_woNI[NL*DM*DM];
__device__ __align__(16) u64 g_wdRR[DM*GDEC], g_wdPI[DM*GDEC], g_wdNI[DM*GDEC];

// ---------------- helpers -------------------------------------------------------
__device__ __forceinline__ u64 pk(float lo, float hi) {
    u64 r; asm("mov.b64 %0, {%1, %2};" : "=l"(r) : "f"(lo), "f"(hi)); return r;
}
__device__ __forceinline__ float2 upk(u64 v) {
    float2 f; asm("mov.b64 {%0, %1}, %2;" : "=f"(f.x), "=f"(f.y) : "l"(v)); return f;
}
__device__ __forceinline__ void fma2(u64& acc, u64 a, u64 b) {
    asm("fma.rn.f32x2 %0, %1, %2, %0;" : "+l"(acc) : "l"(a), "l"(b));
}
__device__ __forceinline__ void cp16(u64* smem_dst, const u64* gsrc) {
    unsigned sa = (unsigned)__cvta_generic_to_shared(smem_dst);
    asm volatile("cp.async.cg.shared.global [%0], [%1], 16;" :: "r"(sa), "l"(gsrc));
}
__device__ __forceinline__ float gelu_tanh(float x) {
    float x3 = x * x * x;
    float t  = 0.7978845608028654f * fmaf(0.044715f, x3, x);
    float th;
    asm("tanh.approx.f32 %0, %1;" : "=f"(th) : "f"(t));
    return 0.5f * x * (1.0f + th);
}

// ---------------- S4D coefficient precompute ------------------------------------
__global__ void precompute_kernel(const float* __restrict__ log_dt,
                                  const float* __restrict__ log_A_real,
                                  const float* __restrict__ A_imag,
                                  const float* __restrict__ C_r,
                                  const float* __restrict__ C_i)
{
    int idx = blockIdx.x * blockDim.x + threadIdx.x;
    if (idx >= NL*DM*NST) return;
    int h = (idx / NST) % DM;
    int l = idx / (NST*DM);
    double dt  = exp((double)log_dt[l*DM + h]);
    double Are = -exp((double)log_A_real[idx]);
    double Aim = (double)A_imag[idx];
    double dre = Are * dt, dim = Aim * dt;
    double er  = exp(dre);
    double arr = er * cos(dim);
    double aii = er * sin(dim);
    g_ar[idx] = (float)arr;
    g_ai[idx] = (float)aii;
    double e1r = arr - 1.0, e1i = aii;
    double den = Are*Are + Aim*Aim;
    double qr  = (e1r*Are + e1i*Aim) / den;
    double qi  = (e1i*Are - e1r*Aim) / den;
    double cr  = (double)C_r[idx], ci = (double)C_i[idx];
    g_cr[idx] = (float)(cr*qr - ci*qi);
    g_ci[idx] = (float)(cr*qi + ci*qr);
}

// ---------------- input split: x interleaved -> padded u64 t-pair arrays --------
__global__ void split_x_kernel(const float4* __restrict__ x4)
{
    long idx = (long)blockIdx.x * blockDim.x + threadIdx.x;
    if (idx >= (long)BATCH*KENC*TP) return;
    int p = idx % TP;
    int d = (idx / TP) % KENC;
    int b = idx / ((long)TP*KENC);
    u64 xr = 0, xi = 0;
    if (d < DIN) {
        float4 v = x4[(long)(b*DIN + d)*1024 + p];  // (r0,i0,r1,i1)
        xr = pk(v.x, v.z);
        xi = pk(v.y, v.w);
    }
    g_xr[idx] = xr;
    g_xi[idx] = xi;
}

// ---------------- weight prepack kernels -----------------------------------------
__global__ void pack_enc(const float* __restrict__ Wr, const float* __restrict__ Wi)
{
    int idx = blockIdx.x * blockDim.x + threadIdx.x;
    if (idx >= KENC*DM) return;
    int k = idx / DM, g = idx % DM;
    float wr = 0.f, wi = 0.f;
    if (k < DIN) { wr = Wr[(long)g*DIN + k]; wi = Wi[(long)g*DIN + k]; }
    g_weRR[idx] = pk(wr, wr);
    g_wePI[idx] = pk(wi, wi);
    g_weNI[idx] = pk(-wi, -wi);
}
__global__ void pack_out(const float* __restrict__ Wr, const float* __restrict__ Wi)
{
    int idx = blockIdx.x * blockDim.x + threadIdx.x;
    if (idx >= NL*DM*DM) return;
    int g = idx % DM;
    int k = (idx / DM) % DM;
    int l = idx / (DM*DM);
    float wr = Wr[((long)l*DM + g)*DM + k];
    float wi = Wi[((long)l*DM + g)*DM + k];
    g_woRR[idx] = pk(wr, wr);
    g_woPI[idx] = pk(wi, wi);
    g_woNI[idx] = pk(-wi, -wi);
}
__global__ void pack_dec(const float* __restrict__ Wr, const float* __restrict__ Wi)
{
    int idx = blockIdx.x * blockDim.x + threadIdx.x;
    if (idx >= DM*GDEC) return;
    int g = idx % GDEC, k = idx / GDEC;
    float wr = 0.f, wi = 0.f;
    if (g < DIN) { wr = Wr[(long)g*DM + k]; wi = Wi[(long)g*DM + k]; }
    g_wdRR[idx] = pk(wr, wr);
    g_wdPI[idx] = pk(wi, wi);
    g_wdNI[idx] = pk(-wi, -wi);
}

// ---------------- pipelined complex GEMM core ------------------------------------
// Stage smem layout (u64 units): [0,512)=Xr, [512,1024)=Xi, [1024..)=Wrr,Wpi,Wni.
// Tile 64 g x 128 t (64 t-pairs); thread microtile 4 g x 4 t-pairs.
#define STAGE_U64 2560
__device__ __forceinline__ void cgemm_pipe(u64* sm,
    const u64* __restrict__ xr, const u64* __restrict__ xi,   // pre-offset: + tp0
    const u64* __restrict__ w0, const u64* __restrict__ w1,
    const u64* __restrict__ w2,                                // pre-offset: + g0
    int Gs, int nt, u64 accR[4][4], u64 accI[4][4], int tid)
{
    int tx = tid & 15, ty = tid >> 4;
    int row = tid >> 5, c = (tid & 31) * 2;
    long xoff = (long)row * TP + c;
    long woff = (long)row * Gs + c;
    int sof = row*64 + c;
    // prologue: stage 0
    {
        u64* d = sm;
        cp16(d + sof,        xr + xoff);
        cp16(d + 512 + sof,  xi + xoff);
        cp16(d + 1024 + sof, w0 + woff);
        cp16(d + 1536 + sof, w1 + woff);
        cp16(d + 2048 + sof, w2 + woff);
        asm volatile("cp.async.commit_group;");
    }
    for (int s = 0; s < nt; s++) {
        __syncthreads();                         // all done reading buf[(s+1)&1]
        if (s + 1 < nt) {
            u64* d = sm + ((s+1)&1)*STAGE_U64;
            long xo = xoff + (long)(s+1)*8*TP;
            long wo = woff + (long)(s+1)*8*Gs;
            cp16(d + sof,        xr + xo);
            cp16(d + 512 + sof,  xi + xo);
            cp16(d + 1024 + sof, w0 + wo);
            cp16(d + 1536 + sof, w1 + wo);
            cp16(d + 2048 + sof, w2 + wo);
            asm volatile("cp.async.commit_group;");
            asm volatile("cp.async.wait_group 1;");
        } else {
            asm volatile("cp.async.wait_group 0;");
        }
        __syncthreads();                         // stage s visible to all
        const u64* b  = sm + (s&1)*STAGE_U64;
        const u64* bX = b;
        const u64* bY = b + 512;
        const u64* bW0 = b + 1024;
        const u64* bW1 = b + 1536;
        const u64* bW2 = b + 2048;
#pragma unroll
        for (int kk = 0; kk < 8; kk++) {
            u64 xrv[4], xiv[4];
#pragma unroll
            for (int i = 0; i < 4; i++) {
                xrv[i] = bX[kk*64 + tx + 16*i];
                xiv[i] = bY[kk*64 + tx + 16*i];
            }
#pragma unroll
            for (int j = 0; j < 4; j++) {
                u64 wrr = bW0[kk*64 + ty + 16*j];
                u64 wpi = bW1[kk*64 + ty + 16*j];
                u64 wni = bW2[kk*64 + ty + 16*j];
#pragma unroll
                for (int i = 0; i < 4; i++) {
                    fma2(accR[j][i], wrr, xrv[i]);
                    fma2(accR[j][i], wni, xiv[i]);
                    fma2(accI[j][i], wrr, xiv[i]);
                    fma2(accI[j][i], wpi, xrv[i]);
                }
            }
        }
    }
}

// ---------------- encoder ---------------------------------------------------------
__global__ __launch_bounds__(256, 2) void encoder_gemm(
    const float* __restrict__ br, const float* __restrict__ bi)
{
    __shared__ u64 sm[2*STAGE_U64];
    int b  = blockIdx.z;
    int tp0 = blockIdx.x * 64;     // t-pair offset
    int g0 = blockIdx.y * 64;
    int tid = threadIdx.x;
    int tx = tid & 15, ty = tid >> 4;
    u64 accR[4][4], accI[4][4];
#pragma unroll
    for (int j = 0; j < 4; j++)
#pragma unroll
        for (int i = 0; i < 4; i++) { accR[j][i] = 0ull; accI[j][i] = 0ull; }

    const u64* xr = g_xr + (long)b*KENC*TP + tp0;
    const u64* xi = g_xi + (long)b*KENC*TP + tp0;
    cgemm_pipe(sm, xr, xi, g_weRR + g0, g_wePI + g0, g_weNI + g0,
               DM, KENC/8, accR, accI, tid);

#pragma unroll
    for (int j = 0; j < 4; j++) {
        int g = g0 + ty + 16*j;
        float bR = br[g], bI = bi[g];
#pragma unroll
        for (int i = 0; i < 4; i++) {
            int t = 2*(tp0 + tx + 16*i);
            long off = ((long)b*DM + g)*TLEN + t;
            float2 fR = upk(accR[j][i]);
            float2 fI = upk(accI[j][i]);
            *reinterpret_cast<float2*>(g_zr + off) = make_float2(fR.x + bR, fR.y + bR);
            *reinterpret_cast<float2*>(g_zi + off) = make_float2(fI.x + bI, fI.y + bI);
        }
    }
}

// ---------------- per-layer pointwise complex GEMM (DM -> DM) ---------------------
__global__ __launch_bounds__(256, 2) void outlin_gemm(int l,
    const float* __restrict__ br, const float* __restrict__ bi)
{
    __shared__ u64 sm[2*STAGE_U64];
    int b  = blockIdx.z;
    int tp0 = blockIdx.x * 64;
    int g0 = blockIdx.y * 64;
    int tid = threadIdx.x;
    int tx = tid & 15, ty = tid >> 4;
    u64 accR[4][4], accI[4][4];
#pragma unroll
    for (int j = 0; j < 4; j++)
#pragma unroll
        for (int i = 0; i < 4; i++) { accR[j][i] = 0ull; accI[j][i] = 0ull; }

    const u64* xr = reinterpret_cast<const u64*>(g_ygr) + (long)b*DM*TP + tp0;
    const u64* xi = reinterpret_cast<const u64*>(g_ygi) + (long)b*DM*TP + tp0;
    long wb = (long)l*DM*DM + g0;
    cgemm_pipe(sm, xr, xi, g_woRR + wb, g_woPI + wb, g_woNI + wb,
               DM, DM/8, accR, accI, tid);

#pragma unroll
    for (int j = 0; j < 4; j++) {
        int g = g0 + ty + 16*j;
        float bR = br[l*DM + g], bI = bi[l*DM + g];
#pragma unroll
        for (int i = 0; i < 4; i++) {
            int t = 2*(tp0 + tx + 16*i);
            long off = ((long)b*DM + g)*TLEN + t;
            float2 fR = upk(accR[j][i]);
            float2 fI = upk(accI[j][i]);
            *reinterpret_cast<float2*>(g_or + off) = make_float2(fR.x + bR, fR.y + bR);
            *reinterpret_cast<float2*>(g_oi + off) = make_float2(fI.x + bI, fI.y + bI);
        }
    }
}

// ---------------- decoder ---------------------------------------------------------
__global__ __launch_bounds__(256, 2) void decoder_gemm(
    const float* __restrict__ br, const float* __restrict__ bi,
    float4* __restrict__ out)
{
    __shared__ u64 sm[2*STAGE_U64];
    int b  = blockIdx.z;
    int tp0 = blockIdx.x * 64;
    int g0 = blockIdx.y * 64;
    int tid = threadIdx.x;
    int tx = tid & 15, ty = tid >> 4;
    u64 accR[4][4], accI[4][4];
#pragma unroll
    for (int j = 0; j < 4; j++)
#pragma unroll
        for (int i = 0; i < 4; i++) { accR[j][i] = 0ull; accI[j][i] = 0ull; }

    const u64* xr = reinterpret_cast<const u64*>(g_zr) + (long)b*DM*TP + tp0;
    const u64* xi = reinterpret_cast<const u64*>(g_zi) + (long)b*DM*TP + tp0;
    cgemm_pipe(sm, xr, xi, g_wdRR + g0, g_wdPI + g0, g_wdNI + g0,
               GDEC, DM/8, accR, accI, tid);

#pragma unroll
    for (int j = 0; j < 4; j++) {
        int g = g0 + ty + 16*j;
        if (g >= DIN) continue;
        float bR = br[g], bI = bi[g];
#pragma unroll
        for (int i = 0; i < 4; i++) {
            int t = 2*(tp0 + tx + 16*i);
            float2 fR = upk(accR[j][i]);
            float2 fI = upk(accI[j][i]);
            out[(((long)b*DIN + g)*TLEN + t) >> 1] =
                make_float4(fR.x + bR, fI.x + bI, fR.y + bR, fI.y + bI);
        }
    }
}

// ---------------- per-layer S4D scan + D-skip + gelu (warp = one (b,h)) ----------
__global__ __launch_bounds__(128) void scan_kernel(int layer, const float* __restrict__ Dvec)
{
    __shared__ float2 uS[4][32];
    __shared__ float2 prodS[4][32][34];
    int wid  = threadIdx.x >> 5;
    int lane = threadIdx.x & 31;
    int ch = blockIdx.x * 4 + wid;
    int b  = ch >> 8;
    int h  = ch & 255;
    int pidx = (layer*DM + h)*NST + lane;
    float ar = g_ar[pidx], ai = g_ai[pidx];
    float cr = g_cr[pidx], ci = g_ci[pidx];
    float Dh = Dvec[layer*DM + h];
    long base = ((long)b*DM + h)*TLEN;
    const float* zr = g_zr + base;
    const float* zi = g_zi + base;
    float* yro = g_ygr + base;
    float* yio = g_ygi + base;

    float sr = 0.f, si = 0.f;
    for (int t0 = 0; t0 < TLEN; t0 += 32) {
        float ur_l = zr[t0 + lane];
        float ui_l = zi[t0 + lane];
        uS[wid][lane] = make_float2(ur_l, ui_l);
        __syncwarp();
#pragma unroll
        for (int j = 0; j < 32; j++) {
            float2 u = uS[wid][j];
            float nsr = fmaf(ar, sr, u.x); nsr = fmaf(-ai, si, nsr);
            float nsi = fmaf(ar, si, u.y); nsi = fmaf( ai, sr, nsi);
            sr = nsr; si = nsi;
            float pr = cr * sr; pr = fmaf(-ci, si, pr);
            float pi = cr * si; pi = fmaf( ci, sr, pi);
            prodS[wid][j][lane] = make_float2(pr, pi);
        }
        __syncwarp();
        float yr = 0.f, yi = 0.f;
#pragma unroll
        for (int q = 0; q < 32; q++) {
            float2 v = prodS[wid][lane][q];
            yr += v.x; yi += v.y;
        }
        yr = fmaf(Dh, ur_l, yr);
        yi = fmaf(Dh, ui_l, yi);
        yro[t0 + lane] = gelu_tanh(yr);
        yio[t0 + lane] = gelu_tanh(yi);
        __syncwarp();
    }
}

// ---------------- residual + complex LayerNorm over channels ----------------------
__global__ __launch_bounds__(256) void ln_kernel(int l,
    const float* __restrict__ gamma_r, const float* __restrict__ gamma_i,
    const float* __restrict__ beta_r,  const float* __restrict__ beta_i)
{
    int b  = blockIdx.y;
    int t0 = blockIdx.x * 32;
    int tt = threadIdx.x & 31;
    int gg = threadIdx.x >> 5;
    int t  = t0 + tt;

    float vr[32], vi[32];
    float sr = 0.f, qr = 0.f, si = 0.f, qi = 0.f;
#pragma unroll
    for (int j = 0; j < 32; j++) {
        int g = gg*32 + j;
        long off = ((long)b*DM + g)*TLEN + t;
        float r  = g_zr[off] + g_or[off];
        float i_ = g_zi[off] + g_oi[off];
        vr[j] = r; vi[j] = i_;
        sr += r;  qr = fmaf(r, r, qr);
        si += i_; qi = fmaf(i_, i_, qi);
    }
    __shared__ float red[4][8][32];
    red[0][gg][tt] = sr; red[1][gg][tt] = qr;
    red[2][gg][tt] = si; red[3][gg][tt] = qi;
    __syncthreads();
    float tsr = 0.f, tqr = 0.f, tsi = 0.f, tqi = 0.f;
#pragma unroll
    for (int k = 0; k < 8; k++) {
        tsr += red[0][k][tt]; tqr += red[1][k][tt];
        tsi += red[2][k][tt]; tqi += red[3][k][tt];
    }
    float mr  = tsr * (1.f/DM), mi_ = tsi * (1.f/DM);
    float var_r = tqr * (1.f/DM) - mr*mr;
    float var_i = tqi * (1.f/DM) - mi_*mi_;
    float rr = rsqrtf(var_r + 1e-5f);
    float ri = rsqrtf(var_i + 1e-5f);
#pragma unroll
    for (int j = 0; j < 32; j++) {
        int g = gg*32 + j;
        long off = ((long)b*DM + g)*TLEN + t;
        g_zr[off] = (vr[j] - mr)  * rr * gamma_r[l*DM + g] + beta_r[l*DM + g];
        g_zi[off] = (vi[j] - mi_) * ri * gamma_i[l*DM + g] + beta_i[l*DM + g];
    }
}

// ---------------- launch ------------------------------------------------------
extern "C" void kernel_launch(void* const* d_in, const int* in_sizes, int n_in,
                              void* d_out, int out_size)
{
    const float* x          = (const float*)d_in[0];
    const float* enc_Wr     = (const float*)d_in[1];
    const float* enc_Wi     = (const float*)d_in[2];
    const float* enc_br     = (const float*)d_in[3];
    const float* enc_bi     = (const float*)d_in[4];
    const float* log_dt     = (const float*)d_in[5];
    const float* log_A_real = (const float*)d_in[6];
    const float* A_imag     = (const float*)d_in[7];
    const float* C_r        = (const float*)d_in[8];
    const float* C_i        = (const float*)d_in[9];
    const float* Dvec       = (const float*)d_in[10];
    const float* out_Wr     = (const float*)d_in[11];
    const float* out_Wi     = (const float*)d_in[12];
    const float* out_br     = (const float*)d_in[13];
    const float* out_bi     = (const float*)d_in[14];
    const float* ln_gamma_r = (const float*)d_in[15];
    const float* ln_gamma_i = (const float*)d_in[16];
    const float* ln_beta_r  = (const float*)d_in[17];
    const float* ln_beta_i  = (const float*)d_in[18];
    const float* dec_Wr     = (const float*)d_in[19];
    const float* dec_Wi     = (const float*)d_in[20];
    const float* dec_br     = (const float*)d_in[21];
    const float* dec_bi     = (const float*)d_in[22];

    precompute_kernel<<<(NL*DM*NST + 255)/256, 256>>>(log_dt, log_A_real, A_imag, C_r, C_i);
    split_x_kernel<<<(int)(((long)BATCH*KENC*TP + 255)/256), 256>>>((const float4*)x);
    pack_enc<<<(KENC*DM + 255)/256, 256>>>(enc_Wr, enc_Wi);
    pack_out<<<(NL*DM*DM + 255)/256, 256>>>(out_Wr, out_Wi);
    pack_dec<<<(DM*GDEC + 255)/256, 256>>>(dec_Wr, dec_Wi);

    encoder_gemm<<<dim3(TLEN/128, DM/64, BATCH), 256>>>(enc_br, enc_bi);

    for (int l = 0; l < NL; l++) {
        scan_kernel<<<(BATCH*DM)/4, 128>>>(l, Dvec);
        outlin_gemm<<<dim3(TLEN/128, DM/64, BATCH), 256>>>(l, out_br, out_bi);
        ln_kernel<<<dim3(TLEN/32, BATCH), 256>>>(l, ln_gamma_r, ln_gamma_i, ln_beta_r, ln_beta_i);
    }

    decoder_gemm<<<dim3(TLEN/128, GDEC/64, BATCH), 256>>>(dec_br, dec_bi, (float4*)d_out);
}